// round 14
// baseline (speedup 1.0000x reference)
#include <cuda_runtime.h>
#include <cuda_fp16.h>
#include <cstdint>

#define B_   4
#define T_   2048
#define C_   1024
#define H_   16
#define D_   64
#define BH_  64
#define M_   8192

typedef __half fp16;

// ---------------- scratch (allocation-free) ----------------
__device__ fp16 g_x [(size_t)M_*C_];
__device__ fp16 g_wa[(size_t)C_*3*C_];           // [K,N]
__device__ fp16 g_wp[(size_t)C_*C_];
__device__ fp16 g_qkv[(size_t)3*BH_*T_*D_];      // [part][bh][t][d], q pre-scaled
__device__ fp16 g_y [(size_t)M_*C_];

#define DI static __device__ __forceinline__

DI uint32_t smaddr(const void* p){ return (uint32_t)__cvta_generic_to_shared(p); }

DI void cpa16(void* dst, const void* src){
    asm volatile("cp.async.cg.shared.global [%0],[%1],16;\n"
        ::"r"(smaddr(dst)),"l"(src));
}
DI void cpcommit(){ asm volatile("cp.async.commit_group;\n"); }
template<int N> DI void cpwait(){ asm volatile("cp.async.wait_group %0;\n"::"n"(N)); }

DI void ldm_x4(uint32_t* r, uint32_t a){
    asm volatile("ldmatrix.sync.aligned.m8n8.x4.shared.b16 {%0,%1,%2,%3},[%4];"
        :"=r"(r[0]),"=r"(r[1]),"=r"(r[2]),"=r"(r[3]):"r"(a));
}
DI void ldm_x4t(uint32_t* r, uint32_t a){
    asm volatile("ldmatrix.sync.aligned.m8n8.x4.trans.shared.b16 {%0,%1,%2,%3},[%4];"
        :"=r"(r[0]),"=r"(r[1]),"=r"(r[2]),"=r"(r[3]):"r"(a));
}
DI void mma16816(float* c, const uint32_t* a, uint32_t b0, uint32_t b1){
    asm volatile("mma.sync.aligned.m16n8k16.row.col.f32.f16.f16.f32 "
        "{%0,%1,%2,%3},{%4,%5,%6,%7},{%8,%9},{%0,%1,%2,%3};"
        :"+f"(c[0]),"+f"(c[1]),"+f"(c[2]),"+f"(c[3])
        :"r"(a[0]),"r"(a[1]),"r"(a[2]),"r"(a[3]),"r"(b0),"r"(b1));
}
DI uint32_t pkf2(float x, float y){
    __half2 t = __floats2half2_rn(x, y);
    return *reinterpret_cast<uint32_t*>(&t);
}

// ---------------------------------------------------------------------------
// fp32 -> fp16 convert, all three tensors in ONE launch.
// ---------------------------------------------------------------------------
__global__ void cvt_kernel(const float4* __restrict__ xs,
                           const float4* __restrict__ was,
                           const float4* __restrict__ wps)
{
    int b = blockIdx.x;
    const float4* src; fp16* dst; int i;
    if (b < 8192)       { src = xs;  dst = g_x;  i = b*256 + threadIdx.x; }
    else if (b < 11264) { src = was; dst = g_wa; i = (b-8192)*256 + threadIdx.x; }
    else                { src = wps; dst = g_wp; i = (b-11264)*256 + threadIdx.x; }
    float4 v = src[i];
    *reinterpret_cast<uint2*>(dst + (size_t)i*4) =
        make_uint2(pkf2(v.x, v.y), pkf2(v.z, v.w));
}

// ---------------------------------------------------------------------------
// fp16 GEMM via mma.sync.  128x128 tile, BK=32, 128 threads / 4 warps (2x2),
// warp tile 64x64 -> 32 FLOP per smem byte (2x the 32x32-warp config), so the
// loop is tensor-bound, not smem-bandwidth-bound.  3-stage cp.async pipeline.
// ~175 regs -> 2 CTAs/SM (8 warps) by register file.
// mode 0: x @ W_attn -> qkv scatter (bias; q scaled by 0.125*log2(e))
// mode 1: y @ W_proj -> fp32 out + bias
// ---------------------------------------------------------------------------
#define ASZ (128*40)
#define BSZ (32*136)
#define GSTG (ASZ + BSZ)          // halves per stage
#define GSMEM (3*GSTG*2)          // 56832 bytes, 3 stages

#define QSCALE 0.18033688f        // 0.125 * log2(e); softmax uses exp2

__global__ void __launch_bounds__(128) gemm_kernel(
    int mode, const float* __restrict__ bias, float* __restrict__ out)
{
    const int N = mode ? 1024 : 3072;
    const fp16* __restrict__ A = mode ? g_y  : g_x;
    const fp16* __restrict__ Bm = mode ? g_wp : g_wa;

    extern __shared__ fp16 dyn[];

    int tid = threadIdx.x, lane = tid & 31, wid = tid >> 5;   // 4 warps
    int wm = wid >> 1, wn = wid & 1;                          // 2x2
    int m0 = blockIdx.y * 128, n0 = blockIdx.x * 128;

    float acc[4][8][4];
    #pragma unroll
    for (int a = 0; a < 4; a++)
        #pragma unroll
        for (int b = 0; b < 8; b++)
            #pragma unroll
            for (int c = 0; c < 4; c++) acc[a][b][c] = 0.f;

    int lr = lane & 15, lc = lane >> 4;
    int br = tid >> 2, boff = (tid & 3) << 5;   // B: 32 rows x 128 cols

    auto load_stage = [&](int st, int k0){
        fp16* sA = dyn + st*GSTG;
        fp16* sB = sA + ASZ;
        const fp16* ap = A + (size_t)(m0 + tid)*1024 + k0;   // A: row per thread
        cpa16(sA + tid*40,      ap);
        cpa16(sA + tid*40 + 8,  ap + 8);
        cpa16(sA + tid*40 + 16, ap + 16);
        cpa16(sA + tid*40 + 24, ap + 24);
        const fp16* bp = Bm + (size_t)(k0 + br)*N + n0 + boff;
        cpa16(sB + br*136 + boff,      bp);
        cpa16(sB + br*136 + boff + 8,  bp + 8);
        cpa16(sB + br*136 + boff + 16, bp + 16);
        cpa16(sB + br*136 + boff + 24, bp + 24);
        cpcommit();
    };

    load_stage(0, 0);
    load_stage(1, 32);

    for (int t = 0; t < 32; t++) {
        int cur = t % 3;
        if (t + 2 < 32) load_stage((t+2) % 3, (t+2)*32);
        if (t + 2 < 32) cpwait<2>();
        else if (t + 1 < 32) cpwait<1>();
        else cpwait<0>();
        __syncthreads();

        fp16* sA = dyn + cur*GSTG;
        fp16* sB = sA + ASZ;

        #pragma unroll
        for (int kk = 0; kk < 32; kk += 16) {
            uint32_t af[4][4];
            #pragma unroll
            for (int mi = 0; mi < 4; mi++)
                ldm_x4(af[mi], smaddr(sA + (wm*64 + mi*16 + lr)*40 + kk + lc*8));
            #pragma unroll
            for (int half = 0; half < 2; half++) {
                uint32_t bf[4][2];
                #pragma unroll
                for (int p = 0; p < 2; p++) {
                    uint32_t tt[4];
                    ldm_x4t(tt, smaddr(sB + (kk + lr)*136 + wn*64 + half*32 + p*16 + lc*8));
                    bf[2*p][0]=tt[0]; bf[2*p][1]=tt[1];
                    bf[2*p+1][0]=tt[2]; bf[2*p+1][1]=tt[3];
                }
                #pragma unroll
                for (int mi = 0; mi < 4; mi++)
                    #pragma unroll
                    for (int ni = 0; ni < 4; ni++)
                        mma16816(acc[mi][half*4+ni], af[mi], bf[ni][0], bf[ni][1]);
            }
        }
        __syncthreads();
    }

    int lr4 = lane >> 2, lc2 = (lane & 3) << 1;
    if (mode == 0) {
        #pragma unroll
        for (int mi = 0; mi < 4; mi++) {
            int r0 = m0 + wm*64 + mi*16 + lr4;
            #pragma unroll
            for (int nj = 0; nj < 8; nj++) {
                int col = n0 + wn*64 + nj*8 + lc2;
                float b0v = bias[col], b1v = bias[col+1];
                int part = col >> 10, within = col & 1023;
                int h = within >> 6, d = within & 63;
                float sc = (part == 0) ? QSCALE : 1.0f;
                #pragma unroll
                for (int e = 0; e < 2; e++) {
                    int r = r0 + e*8;
                    int bb = r >> 11, tt2 = r & 2047;
                    size_t idx = (((size_t)part*BH_ + bb*H_ + h)*T_ + tt2)*D_ + d;
                    *(uint32_t*)(g_qkv + idx) =
                        pkf2((acc[mi][nj][2*e]   + b0v)*sc,
                             (acc[mi][nj][2*e+1] + b1v)*sc);
                }
            }
        }
    } else {
        #pragma unroll
        for (int mi = 0; mi < 4; mi++) {
            int r0 = m0 + wm*64 + mi*16 + lr4;
            #pragma unroll
            for (int nj = 0; nj < 8; nj++) {
                int col = n0 + wn*64 + nj*8 + lc2;
                float b0v = bias[col], b1v = bias[col+1];
                #pragma unroll
                for (int e = 0; e < 2; e++) {
                    int r = r0 + e*8;
                    *(float2*)(out + (size_t)r*1024 + col) =
                        make_float2(acc[mi][nj][2*e] + b0v,
                                    acc[mi][nj][2*e+1] + b1v);
                }
            }
        }
    }
}

// ---------------------------------------------------------------------------
// FlashAttention-2, fp16 mma.sync, 2-stage cp.async K/V pipeline,
// __launch_bounds__(256,2), exp2f softmax (Q pre-scaled).  R13-proven.
// ---------------------------------------------------------------------------
#define KSZ (64*72)
#define ASTG (2*KSZ)    // k, v per stage; 2 stages = 36864 bytes

__global__ void __launch_bounds__(256,2) attn_kernel()
{
    extern __shared__ fp16 dyn[];

    int tid = threadIdx.x, lane = tid & 31, w = tid >> 5;
    int qt = 15 - (int)blockIdx.x;
    int bh = blockIdx.y;

    const fp16* Qg = g_qkv + (size_t)bh*T_*D_ + (size_t)qt*128*D_;
    const fp16* Kg = g_qkv + ((size_t)BH_   + bh)*T_*D_;
    const fp16* Vg = g_qkv + ((size_t)2*BH_ + bh)*T_*D_;

    fp16* sQ = dyn;
    #pragma unroll
    for (int q = 0; q < 4; q++) {
        int c = tid + q*256;
        int r = c >> 3, off = (c & 7) << 3;
        cpa16(sQ + r*72 + off, Qg + (size_t)r*64 + off);
    }
    cpcommit();
    cpwait<0>();
    __syncthreads();

    int lr = lane & 15, lc = lane >> 4;
    uint32_t qf[4][4];
    #pragma unroll
    for (int kk = 0; kk < 4; kk++)
        ldm_x4(qf[kk], smaddr(sQ + (w*16 + lr)*72 + kk*16 + lc*8));
    __syncthreads();

    auto load_kv = [&](int st, int kt){
        fp16* sK = dyn + st*ASTG;
        fp16* sV = sK + KSZ;
        size_t base = (size_t)kt*64*D_;
        #pragma unroll
        for (int q = 0; q < 2; q++) {
            int c = tid + q*256;
            int r = c >> 3, off = (c & 7) << 3;
            size_t s = base + (size_t)r*64 + off;
            int ds = r*72 + off;
            cpa16(sK + ds, Kg + s);
            cpa16(sV + ds, Vg + s);
        }
        cpcommit();
    };

    float o[8][4];
    #pragma unroll
    for (int j = 0; j < 8; j++)
        #pragma unroll
        for (int e = 0; e < 4; e++) o[j][e] = 0.f;
    float mrow[2] = {-1e30f, -1e30f}, lrow[2] = {0.f, 0.f};

    int kend = 2*qt + 1;
    load_kv(0, 0);

    for (int kt = 0; kt <= kend; kt++) {
        int cur = kt & 1;
        if (kt < kend) load_kv(cur ^ 1, kt + 1);
        if (kt < kend) cpwait<1>(); else cpwait<0>();
        __syncthreads();

        fp16* sK = dyn + cur*ASTG;
        fp16* sV = sK + KSZ;

        float s[8][4];
        #pragma unroll
        for (int j = 0; j < 8; j++)
            #pragma unroll
            for (int e = 0; e < 4; e++) s[j][e] = 0.f;
        #pragma unroll
        for (int kk = 0; kk < 4; kk++) {
            #pragma unroll
            for (int p2 = 0; p2 < 4; p2++) {
                uint32_t kf[4];
                int nrow = p2*16 + lc*8 + (lane & 7);
                int koff = kk*16 + ((lane >> 3) & 1)*8;
                ldm_x4(kf, smaddr(sK + nrow*72 + koff));
                mma16816(s[2*p2],   qf[kk], kf[0], kf[1]);
                mma16816(s[2*p2+1], qf[kk], kf[2], kf[3]);
            }
        }

        if (kt >= 2*qt) {
            int rowb = qt*128 + w*16 + (lane >> 2);
            int colb = kt*64 + ((lane & 3) << 1);
            #pragma unroll
            for (int j = 0; j < 8; j++)
                #pragma unroll
                for (int e = 0; e < 4; e++) {
                    int row = rowb + (e >> 1)*8;
                    int col = colb + j*8 + (e & 1);
                    if (col > row) s[j][e] = -1e30f;
                }
        }

        // online softmax in log2 domain
        #pragma unroll
        for (int e = 0; e < 2; e++) {
            float mx = -1e30f;
            #pragma unroll
            for (int j = 0; j < 8; j++)
                mx = fmaxf(mx, fmaxf(s[j][2*e], s[j][2*e+1]));
            mx = fmaxf(mx, __shfl_xor_sync(0xffffffffu, mx, 1));
            mx = fmaxf(mx, __shfl_xor_sync(0xffffffffu, mx, 2));
            float mn = fmaxf(mrow[e], mx);
            float corr = exp2f(mrow[e] - mn);
            mrow[e] = mn;
            float sum = 0.f;
            #pragma unroll
            for (int j = 0; j < 8; j++) {
                float p0 = exp2f(s[j][2*e]   - mn);
                float p1 = exp2f(s[j][2*e+1] - mn);
                s[j][2*e] = p0; s[j][2*e+1] = p1;
                sum += p0 + p1;
            }
            sum += __shfl_xor_sync(0xffffffffu, sum, 1);
            sum += __shfl_xor_sync(0xffffffffu, sum, 2);
            lrow[e] = lrow[e]*corr + sum;
            #pragma unroll
            for (int j = 0; j < 8; j++) { o[j][2*e] *= corr; o[j][2*e+1] *= corr; }
        }

        #pragma unroll
        for (int kk = 0; kk < 4; kk++) {
            uint32_t pf[4];
            #pragma unroll
            for (int u = 0; u < 2; u++) {
                pf[2*u]   = pkf2(s[2*kk+u][0], s[2*kk+u][1]);
                pf[2*u+1] = pkf2(s[2*kk+u][2], s[2*kk+u][3]);
            }
            #pragma unroll
            for (int p2 = 0; p2 < 4; p2++) {
                uint32_t vf[4];
                ldm_x4t(vf, smaddr(sV + (kk*16 + lr)*72 + p2*16 + lc*8));
                mma16816(o[2*p2],   pf, vf[0], vf[1]);
                mma16816(o[2*p2+1], pf, vf[2], vf[3]);
            }
        }
        __syncthreads();
    }

    int b = bh >> 4, h = bh & 15;
    #pragma unroll
    for (int e = 0; e < 2; e++) {
        float inv = 1.f / lrow[e];
        int t = qt*128 + w*16 + (lane >> 2) + e*8;
        fp16* y = g_y + ((size_t)b*T_ + t)*C_ + h*64;
        #pragma unroll
        for (int j = 0; j < 8; j++) {
            int d = j*8 + ((lane & 3) << 1);
            *(uint32_t*)(y + d) = pkf2(o[j][2*e]*inv, o[j][2*e+1]*inv);
        }
    }
}

// ---------------------------------------------------------------------------
extern "C" void kernel_launch(void* const* d_in, const int* in_sizes, int n_in,
                              void* d_out, int out_size)
{
    const float* x      = (const float*)d_in[0];
    const float* w_attn = (const float*)d_in[1];
    const float* b_attn = (const float*)d_in[2];
    const float* w_proj = (const float*)d_in[3];
    const float* b_proj = (const float*)d_in[4];
    float* out = (float*)d_out;
    (void)in_sizes; (void)n_in; (void)out_size;

    cudaFuncSetAttribute(gemm_kernel,
        cudaFuncAttributeMaxDynamicSharedMemorySize, GSMEM);

    cvt_kernel<<<12288, 256>>>((const float4*)x, (const float4*)w_attn,
                               (const float4*)w_proj);
    gemm_kernel<<<dim3(24, 64), 128, GSMEM>>>(0, b_attn, nullptr);
    attn_kernel<<<dim3(16, 64), 256, 2*ASTG*2>>>();
    gemm_kernel<<<dim3(8, 64), 128, GSMEM>>>(1, b_proj, out);
}

// round 15
// speedup vs baseline: 1.1544x; 1.1544x over previous
#include <cuda_runtime.h>
#include <cuda_fp16.h>
#include <cstdint>

#define B_   4
#define T_   2048
#define C_   1024
#define H_   16
#define D_   64
#define BH_  64
#define M_   8192

typedef __half fp16;

// ---------------- scratch (allocation-free) ----------------
__device__ fp16 g_x [(size_t)M_*C_];
__device__ fp16 g_wa[(size_t)C_*3*C_];           // [K,N]
__device__ fp16 g_wp[(size_t)C_*C_];
__device__ fp16 g_qkv[(size_t)3*BH_*T_*D_];      // [part][bh][t][d], q pre-scaled
__device__ fp16 g_y [(size_t)M_*C_];

#define DI static __device__ __forceinline__

DI uint32_t smaddr(const void* p){ return (uint32_t)__cvta_generic_to_shared(p); }

DI void cpa16(void* dst, const void* src){
    asm volatile("cp.async.cg.shared.global [%0],[%1],16;\n"
        ::"r"(smaddr(dst)),"l"(src));
}
DI void cpcommit(){ asm volatile("cp.async.commit_group;\n"); }
template<int N> DI void cpwait(){ asm volatile("cp.async.wait_group %0;\n"::"n"(N)); }

DI void ldm_x4(uint32_t* r, uint32_t a){
    asm volatile("ldmatrix.sync.aligned.m8n8.x4.shared.b16 {%0,%1,%2,%3},[%4];"
        :"=r"(r[0]),"=r"(r[1]),"=r"(r[2]),"=r"(r[3]):"r"(a));
}
DI void ldm_x4t(uint32_t* r, uint32_t a){
    asm volatile("ldmatrix.sync.aligned.m8n8.x4.trans.shared.b16 {%0,%1,%2,%3},[%4];"
        :"=r"(r[0]),"=r"(r[1]),"=r"(r[2]),"=r"(r[3]):"r"(a));
}
DI void mma16816(float* c, const uint32_t* a, uint32_t b0, uint32_t b1){
    asm volatile("mma.sync.aligned.m16n8k16.row.col.f32.f16.f16.f32 "
        "{%0,%1,%2,%3},{%4,%5,%6,%7},{%8,%9},{%0,%1,%2,%3};"
        :"+f"(c[0]),"+f"(c[1]),"+f"(c[2]),"+f"(c[3])
        :"r"(a[0]),"r"(a[1]),"r"(a[2]),"r"(a[3]),"r"(b0),"r"(b1));
}
DI uint32_t pkf2(float x, float y){
    __half2 t = __floats2half2_rn(x, y);
    return *reinterpret_cast<uint32_t*>(&t);
}

// ---------------------------------------------------------------------------
// fp32 -> fp16 convert, all three tensors in ONE launch.
// ---------------------------------------------------------------------------
__global__ void cvt_kernel(const float4* __restrict__ xs,
                           const float4* __restrict__ was,
                           const float4* __restrict__ wps)
{
    int b = blockIdx.x;
    const float4* src; fp16* dst; int i;
    if (b < 8192)       { src = xs;  dst = g_x;  i = b*256 + threadIdx.x; }
    else if (b < 11264) { src = was; dst = g_wa; i = (b-8192)*256 + threadIdx.x; }
    else                { src = wps; dst = g_wp; i = (b-11264)*256 + threadIdx.x; }
    float4 v = src[i];
    *reinterpret_cast<uint2*>(dst + (size_t)i*4) =
        make_uint2(pkf2(v.x, v.y), pkf2(v.z, v.w));
}

// ---------------------------------------------------------------------------
// fp16 GEMM via mma.sync, templated on warp-tile N width WNW.
// Tile 128 x (4*WNW), BK=32, 512 threads / 16 warps (4x4), warp tile 32xWNW.
// WNW=64: 21.3 FLOP/smem-byte (QKV).  WNW=32: R10-proven config (proj).
// 3-stage cp.async pipeline.
// mode 0: x @ W_attn -> qkv scatter (bias; q scaled by 0.125*log2(e))
// mode 1: y @ W_proj -> fp32 out + bias
// ---------------------------------------------------------------------------
#define QSCALE 0.18033688f        // 0.125 * log2(e); softmax uses exp2

template<int WNW>
__global__ void __launch_bounds__(512,1) gemm_kernel(
    int mode, const float* __restrict__ bias, float* __restrict__ out)
{
    constexpr int BN   = 4*WNW;          // block tile N
    constexpr int BROW = BN + 8;         // B smem row stride (halves)
    constexpr int ASZ_ = 128*40;
    constexpr int GSTG_ = ASZ_ + 32*BROW;
    constexpr int NH   = WNW/32;         // B halves per warp tile
    const int N = mode ? 1024 : 3072;
    const fp16* __restrict__ A = mode ? g_y  : g_x;
    const fp16* __restrict__ Bm = mode ? g_wp : g_wa;

    extern __shared__ fp16 dyn[];

    int tid = threadIdx.x, lane = tid & 31, wid = tid >> 5;   // 16 warps
    int wm = wid >> 2, wn = wid & 3;                          // 4x4
    int m0 = blockIdx.y * 128, n0 = blockIdx.x * BN;

    float acc[2][WNW/8][4];
    #pragma unroll
    for (int a = 0; a < 2; a++)
        #pragma unroll
        for (int b = 0; b < WNW/8; b++)
            #pragma unroll
            for (int c = 0; c < 4; c++) acc[a][b][c] = 0.f;

    int lr = lane & 15, lc = lane >> 4;
    int ar = tid >> 2, aoff = (tid & 3) << 3;       // A: 128 rows x 32 cols
    int br = tid >> 4;                              // B: 32 rows x BN cols
    int bcol = (tid & 15) * 8 * (BN/128);

    auto load_stage = [&](int st, int k0){
        fp16* sA = dyn + st*GSTG_;
        fp16* sB = sA + ASZ_;
        cpa16(sA + ar*40 + aoff, A + (size_t)(m0 + ar)*1024 + k0 + aoff);
        const fp16* bp = Bm + (size_t)(k0 + br)*N + n0 + bcol;
        #pragma unroll
        for (int c = 0; c < BN/128; c++)
            cpa16(sB + br*BROW + bcol + 8*c, bp + 8*c);
        cpcommit();
    };

    load_stage(0, 0);
    load_stage(1, 32);

    for (int t = 0; t < 32; t++) {
        int cur = t % 3;
        if (t + 2 < 32) load_stage((t+2) % 3, (t+2)*32);
        if (t + 2 < 32) cpwait<2>();
        else if (t + 1 < 32) cpwait<1>();
        else cpwait<0>();
        __syncthreads();

        fp16* sA = dyn + cur*GSTG_;
        fp16* sB = sA + ASZ_;

        #pragma unroll
        for (int kk = 0; kk < 32; kk += 16) {
            uint32_t af[2][4];
            #pragma unroll
            for (int mi = 0; mi < 2; mi++)
                ldm_x4(af[mi], smaddr(sA + (wm*32 + mi*16 + lr)*40 + kk + lc*8));
            #pragma unroll
            for (int half = 0; half < NH; half++) {
                uint32_t bf[4][2];
                #pragma unroll
                for (int p = 0; p < 2; p++) {
                    uint32_t tt[4];
                    ldm_x4t(tt, smaddr(sB + (kk + lr)*BROW + wn*WNW + half*32 + p*16 + lc*8));
                    bf[2*p][0]=tt[0]; bf[2*p][1]=tt[1];
                    bf[2*p+1][0]=tt[2]; bf[2*p+1][1]=tt[3];
                }
                #pragma unroll
                for (int mi = 0; mi < 2; mi++)
                    #pragma unroll
                    for (int ni = 0; ni < 4; ni++)
                        mma16816(acc[mi][half*4+ni], af[mi], bf[ni][0], bf[ni][1]);
            }
        }
        __syncthreads();
    }

    int lr4 = lane >> 2, lc2 = (lane & 3) << 1;
    if (mode == 0) {
        #pragma unroll
        for (int mi = 0; mi < 2; mi++) {
            int r0 = m0 + wm*32 + mi*16 + lr4;
            #pragma unroll
            for (int nj = 0; nj < WNW/8; nj++) {
                int col = n0 + wn*WNW + nj*8 + lc2;
                float b0v = bias[col], b1v = bias[col+1];
                int part = col >> 10, within = col & 1023;
                int h = within >> 6, d = within & 63;
                float sc = (part == 0) ? QSCALE : 1.0f;
                #pragma unroll
                for (int e = 0; e < 2; e++) {
                    int r = r0 + e*8;
                    int bb = r >> 11, tt2 = r & 2047;
                    size_t idx = (((size_t)part*BH_ + bb*H_ + h)*T_ + tt2)*D_ + d;
                    *(uint32_t*)(g_qkv + idx) =
                        pkf2((acc[mi][nj][2*e]   + b0v)*sc,
                             (acc[mi][nj][2*e+1] + b1v)*sc);
                }
            }
        }
    } else {
        #pragma unroll
        for (int mi = 0; mi < 2; mi++) {
            int r0 = m0 + wm*32 + mi*16 + lr4;
            #pragma unroll
            for (int nj = 0; nj < WNW/8; nj++) {
                int col = n0 + wn*WNW + nj*8 + lc2;
                float b0v = bias[col], b1v = bias[col+1];
                #pragma unroll
                for (int e = 0; e < 2; e++) {
                    int r = r0 + e*8;
                    *(float2*)(out + (size_t)r*1024 + col) =
                        make_float2(acc[mi][nj][2*e] + b0v,
                                    acc[mi][nj][2*e+1] + b1v);
                }
            }
        }
    }
}

#define GSMEM64 (3*(128*40 + 32*264)*2)    // 81408 B  (WNW=64)
#define GSMEM32 (3*(128*40 + 32*136)*2)    // 56832 B  (WNW=32)

// ---------------------------------------------------------------------------
// FlashAttention-2, fp16 mma.sync, 2-stage cp.async K/V pipeline,
// __launch_bounds__(256,2), exp2f softmax (Q pre-scaled).  R13-proven.
// ---------------------------------------------------------------------------
#define KSZ (64*72)
#define ASTG (2*KSZ)    // k, v per stage; 2 stages = 36864 bytes

__global__ void __launch_bounds__(256,2) attn_kernel()
{
    extern __shared__ fp16 dyn[];

    int tid = threadIdx.x, lane = tid & 31, w = tid >> 5;
    int qt = 15 - (int)blockIdx.x;
    int bh = blockIdx.y;

    const fp16* Qg = g_qkv + (size_t)bh*T_*D_ + (size_t)qt*128*D_;
    const fp16* Kg = g_qkv + ((size_t)BH_   + bh)*T_*D_;
    const fp16* Vg = g_qkv + ((size_t)2*BH_ + bh)*T_*D_;

    fp16* sQ = dyn;
    #pragma unroll
    for (int q = 0; q < 4; q++) {
        int c = tid + q*256;
        int r = c >> 3, off = (c & 7) << 3;
        cpa16(sQ + r*72 + off, Qg + (size_t)r*64 + off);
    }
    cpcommit();
    cpwait<0>();
    __syncthreads();

    int lr = lane & 15, lc = lane >> 4;
    uint32_t qf[4][4];
    #pragma unroll
    for (int kk = 0; kk < 4; kk++)
        ldm_x4(qf[kk], smaddr(sQ + (w*16 + lr)*72 + kk*16 + lc*8));
    __syncthreads();

    auto load_kv = [&](int st, int kt){
        fp16* sK = dyn + st*ASTG;
        fp16* sV = sK + KSZ;
        size_t base = (size_t)kt*64*D_;
        #pragma unroll
        for (int q = 0; q < 2; q++) {
            int c = tid + q*256;
            int r = c >> 3, off = (c & 7) << 3;
            size_t s = base + (size_t)r*64 + off;
            int ds = r*72 + off;
            cpa16(sK + ds, Kg + s);
            cpa16(sV + ds, Vg + s);
        }
        cpcommit();
    };

    float o[8][4];
    #pragma unroll
    for (int j = 0; j < 8; j++)
        #pragma unroll
        for (int e = 0; e < 4; e++) o[j][e] = 0.f;
    float mrow[2] = {-1e30f, -1e30f}, lrow[2] = {0.f, 0.f};

    int kend = 2*qt + 1;
    load_kv(0, 0);

    for (int kt = 0; kt <= kend; kt++) {
        int cur = kt & 1;
        if (kt < kend) load_kv(cur ^ 1, kt + 1);
        if (kt < kend) cpwait<1>(); else cpwait<0>();
        __syncthreads();

        fp16* sK = dyn + cur*ASTG;
        fp16* sV = sK + KSZ;

        float s[8][4];
        #pragma unroll
        for (int j = 0; j < 8; j++)
            #pragma unroll
            for (int e = 0; e < 4; e++) s[j][e] = 0.f;
        #pragma unroll
        for (int kk = 0; kk < 4; kk++) {
            #pragma unroll
            for (int p2 = 0; p2 < 4; p2++) {
                uint32_t kf[4];
                int nrow = p2*16 + lc*8 + (lane & 7);
                int koff = kk*16 + ((lane >> 3) & 1)*8;
                ldm_x4(kf, smaddr(sK + nrow*72 + koff));
                mma16816(s[2*p2],   qf[kk], kf[0], kf[1]);
                mma16816(s[2*p2+1], qf[kk], kf[2], kf[3]);
            }
        }

        if (kt >= 2*qt) {
            int rowb = qt*128 + w*16 + (lane >> 2);
            int colb = kt*64 + ((lane & 3) << 1);
            #pragma unroll
            for (int j = 0; j < 8; j++)
                #pragma unroll
                for (int e = 0; e < 4; e++) {
                    int row = rowb + (e >> 1)*8;
                    int col = colb + j*8 + (e & 1);
                    if (col > row) s[j][e] = -1e30f;
                }
        }

        // online softmax in log2 domain
        #pragma unroll
        for (int e = 0; e < 2; e++) {
            float mx = -1e30f;
            #pragma unroll
            for (int j = 0; j < 8; j++)
                mx = fmaxf(mx, fmaxf(s[j][2*e], s[j][2*e+1]));
            mx = fmaxf(mx, __shfl_xor_sync(0xffffffffu, mx, 1));
            mx = fmaxf(mx, __shfl_xor_sync(0xffffffffu, mx, 2));
            float mn = fmaxf(mrow[e], mx);
            float corr = exp2f(mrow[e] - mn);
            mrow[e] = mn;
            float sum = 0.f;
            #pragma unroll
            for (int j = 0; j < 8; j++) {
                float p0 = exp2f(s[j][2*e]   - mn);
                float p1 = exp2f(s[j][2*e+1] - mn);
                s[j][2*e] = p0; s[j][2*e+1] = p1;
                sum += p0 + p1;
            }
            sum += __shfl_xor_sync(0xffffffffu, sum, 1);
            sum += __shfl_xor_sync(0xffffffffu, sum, 2);
            lrow[e] = lrow[e]*corr + sum;
            #pragma unroll
            for (int j = 0; j < 8; j++) { o[j][2*e] *= corr; o[j][2*e+1] *= corr; }
        }

        #pragma unroll
        for (int kk = 0; kk < 4; kk++) {
            uint32_t pf[4];
            #pragma unroll
            for (int u = 0; u < 2; u++) {
                pf[2*u]   = pkf2(s[2*kk+u][0], s[2*kk+u][1]);
                pf[2*u+1] = pkf2(s[2*kk+u][2], s[2*kk+u][3]);
            }
            #pragma unroll
            for (int p2 = 0; p2 < 4; p2++) {
                uint32_t vf[4];
                ldm_x4t(vf, smaddr(sV + (kk*16 + lr)*72 + p2*16 + lc*8));
                mma16816(o[2*p2],   pf, vf[0], vf[1]);
                mma16816(o[2*p2+1], pf, vf[2], vf[3]);
            }
        }
        __syncthreads();
    }

    int b = bh >> 4, h = bh & 15;
    #pragma unroll
    for (int e = 0; e < 2; e++) {
        float inv = 1.f / lrow[e];
        int t = qt*128 + w*16 + (lane >> 2) + e*8;
        fp16* y = g_y + ((size_t)b*T_ + t)*C_ + h*64;
        #pragma unroll
        for (int j = 0; j < 8; j++) {
            int d = j*8 + ((lane & 3) << 1);
            *(uint32_t*)(y + d) = pkf2(o[j][2*e]*inv, o[j][2*e+1]*inv);
        }
    }
}

// ---------------------------------------------------------------------------
extern "C" void kernel_launch(void* const* d_in, const int* in_sizes, int n_in,
                              void* d_out, int out_size)
{
    const float* x      = (const float*)d_in[0];
    const float* w_attn = (const float*)d_in[1];
    const float* b_attn = (const float*)d_in[2];
    const float* w_proj = (const float*)d_in[3];
    const float* b_proj = (const float*)d_in[4];
    float* out = (float*)d_out;
    (void)in_sizes; (void)n_in; (void)out_size;

    cudaFuncSetAttribute(gemm_kernel<64>,
        cudaFuncAttributeMaxDynamicSharedMemorySize, GSMEM64);
    cudaFuncSetAttribute(gemm_kernel<32>,
        cudaFuncAttributeMaxDynamicSharedMemorySize, GSMEM32);

    cvt_kernel<<<12288, 256>>>((const float4*)x, (const float4*)w_attn,
                               (const float4*)w_proj);
    gemm_kernel<64><<<dim3(12, 64), 512, GSMEM64>>>(0, b_attn, nullptr);
    attn_kernel<<<dim3(16, 64), 256, 2*ASTG*2>>>();
    gemm_kernel<32><<<dim3(8, 64), 512, GSMEM32>>>(1, b_proj, out);
}

// round 16
// speedup vs baseline: 1.2407x; 1.0747x over previous
#include <cuda_runtime.h>
#include <cuda_fp16.h>
#include <cstdint>

#define B_   4
#define T_   2048
#define C_   1024
#define H_   16
#define D_   64
#define BH_  64
#define M_   8192

typedef __half fp16;

// ---------------- scratch (allocation-free) ----------------
__device__ fp16 g_x [(size_t)M_*C_];
__device__ fp16 g_wa[(size_t)C_*3*C_];           // [K,N]
__device__ fp16 g_wp[(size_t)C_*C_];
__device__ fp16 g_qkv[(size_t)3*BH_*T_*D_];      // [part][bh][t][d], q pre-scaled
__device__ fp16 g_y [(size_t)M_*C_];

#define DI static __device__ __forceinline__

DI uint32_t smaddr(const void* p){ return (uint32_t)__cvta_generic_to_shared(p); }

DI void cpa16(void* dst, const void* src){
    asm volatile("cp.async.cg.shared.global [%0],[%1],16;\n"
        ::"r"(smaddr(dst)),"l"(src));
}
DI void cpcommit(){ asm volatile("cp.async.commit_group;\n"); }
template<int N> DI void cpwait(){ asm volatile("cp.async.wait_group %0;\n"::"n"(N)); }

DI void ldm_x4(uint32_t* r, uint32_t a){
    asm volatile("ldmatrix.sync.aligned.m8n8.x4.shared.b16 {%0,%1,%2,%3},[%4];"
        :"=r"(r[0]),"=r"(r[1]),"=r"(r[2]),"=r"(r[3]):"r"(a));
}
DI void ldm_x4t(uint32_t* r, uint32_t a){
    asm volatile("ldmatrix.sync.aligned.m8n8.x4.trans.shared.b16 {%0,%1,%2,%3},[%4];"
        :"=r"(r[0]),"=r"(r[1]),"=r"(r[2]),"=r"(r[3]):"r"(a));
}
DI void mma16816(float* c, const uint32_t* a, uint32_t b0, uint32_t b1){
    asm volatile("mma.sync.aligned.m16n8k16.row.col.f32.f16.f16.f32 "
        "{%0,%1,%2,%3},{%4,%5,%6,%7},{%8,%9},{%0,%1,%2,%3};"
        :"+f"(c[0]),"+f"(c[1]),"+f"(c[2]),"+f"(c[3])
        :"r"(a[0]),"r"(a[1]),"r"(a[2]),"r"(a[3]),"r"(b0),"r"(b1));
}
DI uint32_t pkf2(float x, float y){
    __half2 t = __floats2half2_rn(x, y);
    return *reinterpret_cast<uint32_t*>(&t);
}

// ---------------------------------------------------------------------------
// fp32 -> fp16 convert, all three tensors in ONE launch.
// ---------------------------------------------------------------------------
__global__ void cvt_kernel(const float4* __restrict__ xs,
                           const float4* __restrict__ was,
                           const float4* __restrict__ wps)
{
    int b = blockIdx.x;
    const float4* src; fp16* dst; int i;
    if (b < 8192)       { src = xs;  dst = g_x;  i = b*256 + threadIdx.x; }
    else if (b < 11264) { src = was; dst = g_wa; i = (b-8192)*256 + threadIdx.x; }
    else                { src = wps; dst = g_wp; i = (b-11264)*256 + threadIdx.x; }
    float4 v = src[i];
    *reinterpret_cast<uint2*>(dst + (size_t)i*4) =
        make_uint2(pkf2(v.x, v.y), pkf2(v.z, v.w));
}

// ---------------------------------------------------------------------------
// fp16 GEMM via mma.sync.  128x128 tile, BK=32, 256 threads / 8 warps (4x2),
// warp tile 32x64 -> 21.3 FLOP/smem-byte.  __launch_bounds__(256,2): 2 CTAs/SM
// = 16 warps/SM, live set ~110 regs < 128 cap (no spill).
// 3-stage cp.async pipeline.
// mode 0: x @ W_attn -> qkv scatter (bias; q scaled by 0.125*log2(e))
// mode 1: y @ W_proj -> fp32 out + bias
// ---------------------------------------------------------------------------
#define ASZ (128*40)
#define BSZ (32*136)
#define GSTG (ASZ + BSZ)          // halves per stage
#define GSMEM (3*GSTG*2)          // 56832 bytes, 3 stages

#define QSCALE 0.18033688f        // 0.125 * log2(e); softmax uses exp2

__global__ void __launch_bounds__(256,2) gemm_kernel(
    int mode, const float* __restrict__ bias, float* __restrict__ out)
{
    const int N = mode ? 1024 : 3072;
    const fp16* __restrict__ A = mode ? g_y  : g_x;
    const fp16* __restrict__ Bm = mode ? g_wp : g_wa;

    extern __shared__ fp16 dyn[];

    int tid = threadIdx.x, lane = tid & 31, wid = tid >> 5;   // 8 warps
    int wm = wid >> 1, wn = wid & 1;                          // 4x2
    int m0 = blockIdx.y * 128, n0 = blockIdx.x * 128;

    float acc[2][8][4];
    #pragma unroll
    for (int a = 0; a < 2; a++)
        #pragma unroll
        for (int b = 0; b < 8; b++)
            #pragma unroll
            for (int c = 0; c < 4; c++) acc[a][b][c] = 0.f;

    int lr = lane & 15, lc = lane >> 4;
    int ar = tid >> 1, aoff = (tid & 1) << 4;       // A: 128 rows x 32 cols
    int br = tid >> 3, bcol = (tid & 7) << 4;       // B: 32 rows x 128 cols

    auto load_stage = [&](int st, int k0){
        fp16* sA = dyn + st*GSTG;
        fp16* sB = sA + ASZ;
        size_t asrc = (size_t)(m0 + ar)*1024 + k0 + aoff;
        cpa16(sA + ar*40 + aoff,     A + asrc);
        cpa16(sA + ar*40 + aoff + 8, A + asrc + 8);
        const fp16* bp = Bm + (size_t)(k0 + br)*N + n0 + bcol;
        cpa16(sB + br*136 + bcol,     bp);
        cpa16(sB + br*136 + bcol + 8, bp + 8);
        cpcommit();
    };

    load_stage(0, 0);
    load_stage(1, 32);

    for (int t = 0; t < 32; t++) {
        int cur = t % 3;
        if (t + 2 < 32) load_stage((t+2) % 3, (t+2)*32);
        if (t + 2 < 32) cpwait<2>();
        else if (t + 1 < 32) cpwait<1>();
        else cpwait<0>();
        __syncthreads();

        fp16* sA = dyn + cur*GSTG;
        fp16* sB = sA + ASZ;

        #pragma unroll
        for (int kk = 0; kk < 32; kk += 16) {
            uint32_t af[2][4];
            #pragma unroll
            for (int mi = 0; mi < 2; mi++)
                ldm_x4(af[mi], smaddr(sA + (wm*32 + mi*16 + lr)*40 + kk + lc*8));
            #pragma unroll
            for (int half = 0; half < 2; half++) {
                uint32_t bf[4][2];
                #pragma unroll
                for (int p = 0; p < 2; p++) {
                    uint32_t tt[4];
                    ldm_x4t(tt, smaddr(sB + (kk + lr)*136 + wn*64 + half*32 + p*16 + lc*8));
                    bf[2*p][0]=tt[0]; bf[2*p][1]=tt[1];
                    bf[2*p+1][0]=tt[2]; bf[2*p+1][1]=tt[3];
                }
                #pragma unroll
                for (int mi = 0; mi < 2; mi++)
                    #pragma unroll
                    for (int ni = 0; ni < 4; ni++)
                        mma16816(acc[mi][half*4+ni], af[mi], bf[ni][0], bf[ni][1]);
            }
        }
        __syncthreads();
    }

    int lr4 = lane >> 2, lc2 = (lane & 3) << 1;
    if (mode == 0) {
        #pragma unroll
        for (int mi = 0; mi < 2; mi++) {
            int r0 = m0 + wm*32 + mi*16 + lr4;
            #pragma unroll
            for (int nj = 0; nj < 8; nj++) {
                int col = n0 + wn*64 + nj*8 + lc2;
                float b0v = bias[col], b1v = bias[col+1];
                int part = col >> 10, within = col & 1023;
                int h = within >> 6, d = within & 63;
                float sc = (part == 0) ? QSCALE : 1.0f;
                #pragma unroll
                for (int e = 0; e < 2; e++) {
                    int r = r0 + e*8;
                    int bb = r >> 11, tt2 = r & 2047;
                    size_t idx = (((size_t)part*BH_ + bb*H_ + h)*T_ + tt2)*D_ + d;
                    *(uint32_t*)(g_qkv + idx) =
                        pkf2((acc[mi][nj][2*e]   + b0v)*sc,
                             (acc[mi][nj][2*e+1] + b1v)*sc);
                }
            }
        }
    } else {
        #pragma unroll
        for (int mi = 0; mi < 2; mi++) {
            int r0 = m0 + wm*32 + mi*16 + lr4;
            #pragma unroll
            for (int nj = 0; nj < 8; nj++) {
                int col = n0 + wn*64 + nj*8 + lc2;
                float b0v = bias[col], b1v = bias[col+1];
                #pragma unroll
                for (int e = 0; e < 2; e++) {
                    int r = r0 + e*8;
                    *(float2*)(out + (size_t)r*1024 + col) =
                        make_float2(acc[mi][nj][2*e] + b0v,
                                    acc[mi][nj][2*e+1] + b1v);
                }
            }
        }
    }
}

// ---------------------------------------------------------------------------
// FlashAttention-2, fp16 mma.sync, 2-stage cp.async K/V pipeline,
// __launch_bounds__(256,2), exp2f softmax (Q pre-scaled).  R13-proven.
// ---------------------------------------------------------------------------
#define KSZ (64*72)
#define ASTG (2*KSZ)    // k, v per stage; 2 stages = 36864 bytes

__global__ void __launch_bounds__(256,2) attn_kernel()
{
    extern __shared__ fp16 dyn[];

    int tid = threadIdx.x, lane = tid & 31, w = tid >> 5;
    int qt = 15 - (int)blockIdx.x;
    int bh = blockIdx.y;

    const fp16* Qg = g_qkv + (size_t)bh*T_*D_ + (size_t)qt*128*D_;
    const fp16* Kg = g_qkv + ((size_t)BH_   + bh)*T_*D_;
    const fp16* Vg = g_qkv + ((size_t)2*BH_ + bh)*T_*D_;

    fp16* sQ = dyn;
    #pragma unroll
    for (int q = 0; q < 4; q++) {
        int c = tid + q*256;
        int r = c >> 3, off = (c & 7) << 3;
        cpa16(sQ + r*72 + off, Qg + (size_t)r*64 + off);
    }
    cpcommit();
    cpwait<0>();
    __syncthreads();

    int lr = lane & 15, lc = lane >> 4;
    uint32_t qf[4][4];
    #pragma unroll
    for (int kk = 0; kk < 4; kk++)
        ldm_x4(qf[kk], smaddr(sQ + (w*16 + lr)*72 + kk*16 + lc*8));
    __syncthreads();

    auto load_kv = [&](int st, int kt){
        fp16* sK = dyn + st*ASTG;
        fp16* sV = sK + KSZ;
        size_t base = (size_t)kt*64*D_;
        #pragma unroll
        for (int q = 0; q < 2; q++) {
            int c = tid + q*256;
            int r = c >> 3, off = (c & 7) << 3;
            size_t s = base + (size_t)r*64 + off;
            int ds = r*72 + off;
            cpa16(sK + ds, Kg + s);
            cpa16(sV + ds, Vg + s);
        }
        cpcommit();
    };

    float o[8][4];
    #pragma unroll
    for (int j = 0; j < 8; j++)
        #pragma unroll
        for (int e = 0; e < 4; e++) o[j][e] = 0.f;
    float mrow[2] = {-1e30f, -1e30f}, lrow[2] = {0.f, 0.f};

    int kend = 2*qt + 1;
    load_kv(0, 0);

    for (int kt = 0; kt <= kend; kt++) {
        int cur = kt & 1;
        if (kt < kend) load_kv(cur ^ 1, kt + 1);
        if (kt < kend) cpwait<1>(); else cpwait<0>();
        __syncthreads();

        fp16* sK = dyn + cur*ASTG;
        fp16* sV = sK + KSZ;

        float s[8][4];
        #pragma unroll
        for (int j = 0; j < 8; j++)
            #pragma unroll
            for (int e = 0; e < 4; e++) s[j][e] = 0.f;
        #pragma unroll
        for (int kk = 0; kk < 4; kk++) {
            #pragma unroll
            for (int p2 = 0; p2 < 4; p2++) {
                uint32_t kf[4];
                int nrow = p2*16 + lc*8 + (lane & 7);
                int koff = kk*16 + ((lane >> 3) & 1)*8;
                ldm_x4(kf, smaddr(sK + nrow*72 + koff));
                mma16816(s[2*p2],   qf[kk], kf[0], kf[1]);
                mma16816(s[2*p2+1], qf[kk], kf[2], kf[3]);
            }
        }

        if (kt >= 2*qt) {
            int rowb = qt*128 + w*16 + (lane >> 2);
            int colb = kt*64 + ((lane & 3) << 1);
            #pragma unroll
            for (int j = 0; j < 8; j++)
                #pragma unroll
                for (int e = 0; e < 4; e++) {
                    int row = rowb + (e >> 1)*8;
                    int col = colb + j*8 + (e & 1);
                    if (col > row) s[j][e] = -1e30f;
                }
        }

        // online softmax in log2 domain
        #pragma unroll
        for (int e = 0; e < 2; e++) {
            float mx = -1e30f;
            #pragma unroll
            for (int j = 0; j < 8; j++)
                mx = fmaxf(mx, fmaxf(s[j][2*e], s[j][2*e+1]));
            mx = fmaxf(mx, __shfl_xor_sync(0xffffffffu, mx, 1));
            mx = fmaxf(mx, __shfl_xor_sync(0xffffffffu, mx, 2));
            float mn = fmaxf(mrow[e], mx);
            float corr = exp2f(mrow[e] - mn);
            mrow[e] = mn;
            float sum = 0.f;
            #pragma unroll
            for (int j = 0; j < 8; j++) {
                float p0 = exp2f(s[j][2*e]   - mn);
                float p1 = exp2f(s[j][2*e+1] - mn);
                s[j][2*e] = p0; s[j][2*e+1] = p1;
                sum += p0 + p1;
            }
            sum += __shfl_xor_sync(0xffffffffu, sum, 1);
            sum += __shfl_xor_sync(0xffffffffu, sum, 2);
            lrow[e] = lrow[e]*corr + sum;
            #pragma unroll
            for (int j = 0; j < 8; j++) { o[j][2*e] *= corr; o[j][2*e+1] *= corr; }
        }

        #pragma unroll
        for (int kk = 0; kk < 4; kk++) {
            uint32_t pf[4];
            #pragma unroll
            for (int u = 0; u < 2; u++) {
                pf[2*u]   = pkf2(s[2*kk+u][0], s[2*kk+u][1]);
                pf[2*u+1] = pkf2(s[2*kk+u][2], s[2*kk+u][3]);
            }
            #pragma unroll
            for (int p2 = 0; p2 < 4; p2++) {
                uint32_t vf[4];
                ldm_x4t(vf, smaddr(sV + (kk*16 + lr)*72 + p2*16 + lc*8));
                mma16816(o[2*p2],   pf, vf[0], vf[1]);
                mma16816(o[2*p2+1], pf, vf[2], vf[3]);
            }
        }
        __syncthreads();
    }

    int b = bh >> 4, h = bh & 15;
    #pragma unroll
    for (int e = 0; e < 2; e++) {
        float inv = 1.f / lrow[e];
        int t = qt*128 + w*16 + (lane >> 2) + e*8;
        fp16* y = g_y + ((size_t)b*T_ + t)*C_ + h*64;
        #pragma unroll
        for (int j = 0; j < 8; j++) {
            int d = j*8 + ((lane & 3) << 1);
            *(uint32_t*)(y + d) = pkf2(o[j][2*e]*inv, o[j][2*e+1]*inv);
        }
    }
}

// ---------------------------------------------------------------------------
extern "C" void kernel_launch(void* const* d_in, const int* in_sizes, int n_in,
                              void* d_out, int out_size)
{
    const float* x      = (const float*)d_in[0];
    const float* w_attn = (const float*)d_in[1];
    const float* b_attn = (const float*)d_in[2];
    const float* w_proj = (const float*)d_in[3];
    const float* b_proj = (const float*)d_in[4];
    float* out = (float*)d_out;
    (void)in_sizes; (void)n_in; (void)out_size;

    cudaFuncSetAttribute(gemm_kernel,
        cudaFuncAttributeMaxDynamicSharedMemorySize, GSMEM);

    cvt_kernel<<<12288, 256>>>((const float4*)x, (const float4*)w_attn,
                               (const float4*)w_proj);
    gemm_kernel<<<dim3(24, 64), 256, GSMEM>>>(0, b_attn, nullptr);
    attn_kernel<<<dim3(16, 64), 256, 2*ASTG*2>>>();
    gemm_kernel<<<dim3(8, 64), 256, GSMEM>>>(1, b_proj, out);
}

// round 17
// speedup vs baseline: 1.2945x; 1.0434x over previous
#include <cuda_runtime.h>
#include <cuda_fp16.h>
#include <cstdint>

#define B_   4
#define T_   2048
#define C_   1024
#define H_   16
#define D_   64
#define BH_  64
#define M_   8192

typedef __half fp16;

// ---------------- scratch (allocation-free) ----------------
__device__ fp16 g_x [(size_t)M_*C_];
__device__ fp16 g_wa[(size_t)C_*3*C_];           // [K,N]
__device__ fp16 g_wp[(size_t)C_*C_];
__device__ fp16 g_qkv[(size_t)3*BH_*T_*D_];      // [part][bh][t][d], q pre-scaled
__device__ fp16 g_y [(size_t)M_*C_];

#define DI static __device__ __forceinline__

DI uint32_t smaddr(const void* p){ return (uint32_t)__cvta_generic_to_shared(p); }

DI void cpa16(void* dst, const void* src){
    asm volatile("cp.async.cg.shared.global [%0],[%1],16;\n"
        ::"r"(smaddr(dst)),"l"(src));
}
DI void cpcommit(){ asm volatile("cp.async.commit_group;\n"); }
template<int N> DI void cpwait(){ asm volatile("cp.async.wait_group %0;\n"::"n"(N)); }

DI void ldm_x4(uint32_t* r, uint32_t a){
    asm volatile("ldmatrix.sync.aligned.m8n8.x4.shared.b16 {%0,%1,%2,%3},[%4];"
        :"=r"(r[0]),"=r"(r[1]),"=r"(r[2]),"=r"(r[3]):"r"(a));
}
DI void ldm_x4t(uint32_t* r, uint32_t a){
    asm volatile("ldmatrix.sync.aligned.m8n8.x4.trans.shared.b16 {%0,%1,%2,%3},[%4];"
        :"=r"(r[0]),"=r"(r[1]),"=r"(r[2]),"=r"(r[3]):"r"(a));
}
DI void mma16816(float* c, const uint32_t* a, uint32_t b0, uint32_t b1){
    asm volatile("mma.sync.aligned.m16n8k16.row.col.f32.f16.f16.f32 "
        "{%0,%1,%2,%3},{%4,%5,%6,%7},{%8,%9},{%0,%1,%2,%3};"
        :"+f"(c[0]),"+f"(c[1]),"+f"(c[2]),"+f"(c[3])
        :"r"(a[0]),"r"(a[1]),"r"(a[2]),"r"(a[3]),"r"(b0),"r"(b1));
}
DI uint32_t pkf2(float x, float y){
    __half2 t = __floats2half2_rn(x, y);
    return *reinterpret_cast<uint32_t*>(&t);
}

// ---------------------------------------------------------------------------
// fp32 -> fp16 convert, all three tensors in ONE launch.
// ---------------------------------------------------------------------------
__global__ void cvt_kernel(const float4* __restrict__ xs,
                           const float4* __restrict__ was,
                           const float4* __restrict__ wps)
{
    int b = blockIdx.x;
    const float4* src; fp16* dst; int i;
    if (b < 8192)       { src = xs;  dst = g_x;  i = b*256 + threadIdx.x; }
    else if (b < 11264) { src = was; dst = g_wa; i = (b-8192)*256 + threadIdx.x; }
    else                { src = wps; dst = g_wp; i = (b-11264)*256 + threadIdx.x; }
    float4 v = src[i];
    *reinterpret_cast<uint2*>(dst + (size_t)i*4) =
        make_uint2(pkf2(v.x, v.y), pkf2(v.z, v.w));
}

// ---------------------------------------------------------------------------
// fp16 GEMM via mma.sync (R13-proven, best measured).  128x128 tile, BK=32,
// 512 threads / 16 warps (4x4), warp tile 32x32, 3-stage cp.async pipeline.
// mode 0: x @ W_attn -> qkv scatter (bias; q scaled by 0.125*log2(e))
// mode 1: y @ W_proj -> fp32 out + bias
// ---------------------------------------------------------------------------
#define ASZ (128*40)
#define BSZ (32*136)
#define GSTG (ASZ + BSZ)          // halves per stage
#define GSMEM (3*GSTG*2)          // 56832 bytes, 3 stages

#define QSCALE 0.18033688f        // 0.125 * log2(e); softmax uses exp2

__global__ void __launch_bounds__(512,1) gemm_kernel(
    int mode, const float* __restrict__ bias, float* __restrict__ out)
{
    const int N = mode ? 1024 : 3072;
    const fp16* __restrict__ A = mode ? g_y  : g_x;
    const fp16* __restrict__ Bm = mode ? g_wp : g_wa;

    extern __shared__ fp16 dyn[];

    int tid = threadIdx.x, lane = tid & 31, wid = tid >> 5;   // 16 warps
    int wm = wid >> 2, wn = wid & 3;                          // 4x4
    int m0 = blockIdx.y * 128, n0 = blockIdx.x * 128;

    float acc[2][4][4];
    #pragma unroll
    for (int a = 0; a < 2; a++)
        #pragma unroll
        for (int b = 0; b < 4; b++)
            #pragma unroll
            for (int c = 0; c < 4; c++) acc[a][b][c] = 0.f;

    int lr = lane & 15, lc = lane >> 4;
    int ar = tid >> 2, aoff = (tid & 3) << 3;       // 128 rows x 32 cols
    int br = tid >> 4, boff = (tid & 15) << 3;      // 32 rows x 128 cols

    auto load_stage = [&](int st, int k0){
        fp16* sA = dyn + st*GSTG;
        fp16* sB = sA + ASZ;
        cpa16(sA + ar*40 + aoff, A + (size_t)(m0 + ar)*1024 + k0 + aoff);
        cpa16(sB + br*136 + boff, Bm + (size_t)(k0 + br)*N + n0 + boff);
        cpcommit();
    };

    load_stage(0, 0);
    load_stage(1, 32);

    for (int t = 0; t < 32; t++) {
        int cur = t % 3;
        if (t + 2 < 32) load_stage((t+2) % 3, (t+2)*32);
        if (t + 2 < 32) cpwait<2>();
        else if (t + 1 < 32) cpwait<1>();
        else cpwait<0>();
        __syncthreads();

        fp16* sA = dyn + cur*GSTG;
        fp16* sB = sA + ASZ;

        #pragma unroll
        for (int kk = 0; kk < 32; kk += 16) {
            uint32_t af[2][4], bf[4][2];
            #pragma unroll
            for (int mi = 0; mi < 2; mi++)
                ldm_x4(af[mi], smaddr(sA + (wm*32 + mi*16 + lr)*40 + kk + lc*8));
            #pragma unroll
            for (int p = 0; p < 2; p++) {
                uint32_t tt[4];
                ldm_x4t(tt, smaddr(sB + (kk + lr)*136 + wn*32 + p*16 + lc*8));
                bf[2*p][0]=tt[0]; bf[2*p][1]=tt[1];
                bf[2*p+1][0]=tt[2]; bf[2*p+1][1]=tt[3];
            }
            #pragma unroll
            for (int mi = 0; mi < 2; mi++)
                #pragma unroll
                for (int ni = 0; ni < 4; ni++)
                    mma16816(acc[mi][ni], af[mi], bf[ni][0], bf[ni][1]);
        }
        __syncthreads();
    }

    int lr4 = lane >> 2, lc2 = (lane & 3) << 1;
    if (mode == 0) {
        #pragma unroll
        for (int mi = 0; mi < 2; mi++) {
            int r0 = m0 + wm*32 + mi*16 + lr4;
            #pragma unroll
            for (int ni = 0; ni < 4; ni++) {
                int col = n0 + wn*32 + ni*8 + lc2;
                float b0v = bias[col], b1v = bias[col+1];
                int part = col >> 10, within = col & 1023;
                int h = within >> 6, d = within & 63;
                float sc = (part == 0) ? QSCALE : 1.0f;
                #pragma unroll
                for (int e = 0; e < 2; e++) {
                    int r = r0 + e*8;
                    int bb = r >> 11, tt2 = r & 2047;
                    size_t idx = (((size_t)part*BH_ + bb*H_ + h)*T_ + tt2)*D_ + d;
                    *(uint32_t*)(g_qkv + idx) =
                        pkf2((acc[mi][ni][2*e]   + b0v)*sc,
                             (acc[mi][ni][2*e+1] + b1v)*sc);
                }
            }
        }
    } else {
        #pragma unroll
        for (int mi = 0; mi < 2; mi++) {
            int r0 = m0 + wm*32 + mi*16 + lr4;
            #pragma unroll
            for (int ni = 0; ni < 4; ni++) {
                int col = n0 + wn*32 + ni*8 + lc2;
                float b0v = bias[col], b1v = bias[col+1];
                #pragma unroll
                for (int e = 0; e < 2; e++) {
                    int r = r0 + e*8;
                    *(float2*)(out + (size_t)r*1024 + col) =
                        make_float2(acc[mi][ni][2*e] + b0v,
                                    acc[mi][ni][2*e+1] + b1v);
                }
            }
        }
    }
}

// ---------------------------------------------------------------------------
// FlashAttention-2, fp16 mma.sync, 2-stage cp.async K/V pipeline,
// __launch_bounds__(256,2), exp2f softmax.  LOAD-BALANCED: each block runs
// TWO Q-tiles (qt = 15-bx and qt = bx) -> constant 34 inner tiles per block,
// grid (8,64) = 512 uniform blocks (1.73 clean waves at 2 CTAs/SM).
// ---------------------------------------------------------------------------
#define KSZ (64*72)
#define ASTG (2*KSZ)    // k, v per stage; 2 stages = 36864 bytes

__global__ void __launch_bounds__(256,2) attn_kernel()
{
    extern __shared__ fp16 dyn[];

    int tid = threadIdx.x, lane = tid & 31, w = tid >> 5;
    int bx = blockIdx.x;          // 0..7
    int bh = blockIdx.y;

    const fp16* Kg = g_qkv + ((size_t)BH_   + bh)*T_*D_;
    const fp16* Vg = g_qkv + ((size_t)2*BH_ + bh)*T_*D_;
    int lr = lane & 15, lc = lane >> 4;

    for (int half = 0; half < 2; half++) {
        int qt = half ? bx : 15 - bx;

        const fp16* Qg = g_qkv + (size_t)bh*T_*D_ + (size_t)qt*128*D_;

        // stage Q (smem free: trailing barrier of previous kt loop passed)
        fp16* sQ = dyn;
        #pragma unroll
        for (int q = 0; q < 4; q++) {
            int c = tid + q*256;
            int r = c >> 3, off = (c & 7) << 3;
            cpa16(sQ + r*72 + off, Qg + (size_t)r*64 + off);
        }
        cpcommit();
        cpwait<0>();
        __syncthreads();

        uint32_t qf[4][4];
        #pragma unroll
        for (int kk = 0; kk < 4; kk++)
            ldm_x4(qf[kk], smaddr(sQ + (w*16 + lr)*72 + kk*16 + lc*8));
        __syncthreads();

        auto load_kv = [&](int st, int kt){
            fp16* sK = dyn + st*ASTG;
            fp16* sV = sK + KSZ;
            size_t base = (size_t)kt*64*D_;
            #pragma unroll
            for (int q = 0; q < 2; q++) {
                int c = tid + q*256;
                int r = c >> 3, off = (c & 7) << 3;
                size_t s = base + (size_t)r*64 + off;
                int ds = r*72 + off;
                cpa16(sK + ds, Kg + s);
                cpa16(sV + ds, Vg + s);
            }
            cpcommit();
        };

        float o[8][4];
        #pragma unroll
        for (int j = 0; j < 8; j++)
            #pragma unroll
            for (int e = 0; e < 4; e++) o[j][e] = 0.f;
        float mrow[2] = {-1e30f, -1e30f}, lrow[2] = {0.f, 0.f};

        int kend = 2*qt + 1;
        load_kv(0, 0);

        for (int kt = 0; kt <= kend; kt++) {
            int cur = kt & 1;
            if (kt < kend) load_kv(cur ^ 1, kt + 1);
            if (kt < kend) cpwait<1>(); else cpwait<0>();
            __syncthreads();

            fp16* sK = dyn + cur*ASTG;
            fp16* sV = sK + KSZ;

            float s[8][4];
            #pragma unroll
            for (int j = 0; j < 8; j++)
                #pragma unroll
                for (int e = 0; e < 4; e++) s[j][e] = 0.f;
            #pragma unroll
            for (int kk = 0; kk < 4; kk++) {
                #pragma unroll
                for (int p2 = 0; p2 < 4; p2++) {
                    uint32_t kf[4];
                    int nrow = p2*16 + lc*8 + (lane & 7);
                    int koff = kk*16 + ((lane >> 3) & 1)*8;
                    ldm_x4(kf, smaddr(sK + nrow*72 + koff));
                    mma16816(s[2*p2],   qf[kk], kf[0], kf[1]);
                    mma16816(s[2*p2+1], qf[kk], kf[2], kf[3]);
                }
            }

            if (kt >= 2*qt) {
                int rowb = qt*128 + w*16 + (lane >> 2);
                int colb = kt*64 + ((lane & 3) << 1);
                #pragma unroll
                for (int j = 0; j < 8; j++)
                    #pragma unroll
                    for (int e = 0; e < 4; e++) {
                        int row = rowb + (e >> 1)*8;
                        int col = colb + j*8 + (e & 1);
                        if (col > row) s[j][e] = -1e30f;
                    }
            }

            // online softmax in log2 domain
            #pragma unroll
            for (int e = 0; e < 2; e++) {
                float mx = -1e30f;
                #pragma unroll
                for (int j = 0; j < 8; j++)
                    mx = fmaxf(mx, fmaxf(s[j][2*e], s[j][2*e+1]));
                mx = fmaxf(mx, __shfl_xor_sync(0xffffffffu, mx, 1));
                mx = fmaxf(mx, __shfl_xor_sync(0xffffffffu, mx, 2));
                float mn = fmaxf(mrow[e], mx);
                float corr = exp2f(mrow[e] - mn);
                mrow[e] = mn;
                float sum = 0.f;
                #pragma unroll
                for (int j = 0; j < 8; j++) {
                    float p0 = exp2f(s[j][2*e]   - mn);
                    float p1 = exp2f(s[j][2*e+1] - mn);
                    s[j][2*e] = p0; s[j][2*e+1] = p1;
                    sum += p0 + p1;
                }
                sum += __shfl_xor_sync(0xffffffffu, sum, 1);
                sum += __shfl_xor_sync(0xffffffffu, sum, 2);
                lrow[e] = lrow[e]*corr + sum;
                #pragma unroll
                for (int j = 0; j < 8; j++) { o[j][2*e] *= corr; o[j][2*e+1] *= corr; }
            }

            #pragma unroll
            for (int kk = 0; kk < 4; kk++) {
                uint32_t pf[4];
                #pragma unroll
                for (int u = 0; u < 2; u++) {
                    pf[2*u]   = pkf2(s[2*kk+u][0], s[2*kk+u][1]);
                    pf[2*u+1] = pkf2(s[2*kk+u][2], s[2*kk+u][3]);
                }
                #pragma unroll
                for (int p2 = 0; p2 < 4; p2++) {
                    uint32_t vf[4];
                    ldm_x4t(vf, smaddr(sV + (kk*16 + lr)*72 + p2*16 + lc*8));
                    mma16816(o[2*p2],   pf, vf[0], vf[1]);
                    mma16816(o[2*p2+1], pf, vf[2], vf[3]);
                }
            }
            __syncthreads();
        }

        // epilogue: y = O / l (registers -> global, no smem)
        int b = bh >> 4, h = bh & 15;
        #pragma unroll
        for (int e = 0; e < 2; e++) {
            float inv = 1.f / lrow[e];
            int t = qt*128 + w*16 + (lane >> 2) + e*8;
            fp16* y = g_y + ((size_t)b*T_ + t)*C_ + h*64;
            #pragma unroll
            for (int j = 0; j < 8; j++) {
                int d = j*8 + ((lane & 3) << 1);
                *(uint32_t*)(y + d) = pkf2(o[j][2*e]*inv, o[j][2*e+1]*inv);
            }
        }
    }
}

// ---------------------------------------------------------------------------
extern "C" void kernel_launch(void* const* d_in, const int* in_sizes, int n_in,
                              void* d_out, int out_size)
{
    const float* x      = (const float*)d_in[0];
    const float* w_attn = (const float*)d_in[1];
    const float* b_attn = (const float*)d_in[2];
    const float* w_proj = (const float*)d_in[3];
    const float* b_proj = (const float*)d_in[4];
    float* out = (float*)d_out;
    (void)in_sizes; (void)n_in; (void)out_size;

    cudaFuncSetAttribute(gemm_kernel,
        cudaFuncAttributeMaxDynamicSharedMemorySize, GSMEM);

    cvt_kernel<<<12288, 256>>>((const float4*)x, (const float4*)w_attn,
                               (const float4*)w_proj);
    gemm_kernel<<<dim3(24, 64), 512, GSMEM>>>(0, b_attn, nullptr);
    attn_kernel<<<dim3(8, 64), 256, 2*ASTG*2>>>();
    gemm_kernel<<<dim3(8, 64), 512, GSMEM>>>(1, b_proj, out);
}